// round 11
// baseline (speedup 1.0000x reference)
#include <cuda_runtime.h>
#include <math.h>

#define Bsz   2
#define Ls    2048
#define Cdim  1024
#define NH    16
#define HD    64
#define HARM  32
#define TOK   (Bsz*Ls)   // 4096

// ---------------- device scratch ----------------------------------------------------
__device__ float g_w[4][HARM*Cdim];      // w transposed: [h][o]
__device__ float g_Bt[Cdim*96];          // stacked qkv basis, transposed
__device__ float g_BoT[Cdim*HARM];       // basis_o transposed
__device__ float g_R[TOK*96];            // qkv resonances
__device__ float g_qkv[3][TOK*Cdim];     // [0]=q, [1]=k (d-permuted), [2]=V transposed [bh][d][L] (key-permuted)
__device__ float g_att[TOK*Cdim];        // attention output [B,L,C]
__device__ float g_Ro[TOK*HARM];         // output-projection resonance

__device__ __forceinline__ float f2tf32(float f) {
    unsigned r;
    asm("cvt.rna.tf32.f32 %0, %1;" : "=r"(r) : "f"(f));
    return __uint_as_float(r);
}
__device__ __forceinline__ float ex2f(float x) {
    float r; asm("ex2.approx.f32 %0, %1;" : "=f"(r) : "f"(x)); return r;
}

__device__ __forceinline__ void mma_tf32(float d[4], const unsigned a[4],
                                         unsigned b0, unsigned b1) {
    asm("mma.sync.aligned.m16n8k8.row.col.f32.tf32.tf32.f32 "
        "{%0,%1,%2,%3}, {%4,%5,%6,%7}, {%8,%9}, {%0,%1,%2,%3};"
        : "+f"(d[0]), "+f"(d[1]), "+f"(d[2]), "+f"(d[3])
        : "r"(a[0]), "r"(a[1]), "r"(a[2]), "r"(a[3]), "r"(b0), "r"(b1));
}

__device__ __forceinline__ void cp16(float* dst, const float* src) {
    unsigned d = (unsigned)__cvta_generic_to_shared(dst);
    asm volatile("cp.async.cg.shared.global [%0], [%1], 16;" :: "r"(d), "l"(src));
}

// ---------------- kernel 1: w = amp * cos(phase), stored transposed [h][o] ----------
__global__ void k_w(const float* __restrict__ pq, const float* __restrict__ aq,
                    const float* __restrict__ pk, const float* __restrict__ ak,
                    const float* __restrict__ pv, const float* __restrict__ av,
                    const float* __restrict__ po, const float* __restrict__ ao) {
    int i = blockIdx.x * blockDim.x + threadIdx.x;
    int o = i >> 5, h = i & 31;
    int j = h * Cdim + o;
    g_w[0][j] = aq[i] * cosf(pq[i]);
    g_w[1][j] = ak[i] * cosf(pk[i]);
    g_w[2][j] = av[i] * cosf(pv[i]);
    g_w[3][j] = ao[i] * cosf(po[i]);
}

// ---------------- kernel 2: transpose + stack bases ---------------------------------
__global__ void k_tr(const float* __restrict__ bq, const float* __restrict__ bk,
                     const float* __restrict__ bv, const float* __restrict__ bo) {
    int i = blockIdx.x * blockDim.x + threadIdx.x;
    int h = i >> 10, d = i & 1023;
    g_Bt[d*96 + h]      = bq[i];
    g_Bt[d*96 + 32 + h] = bk[i];
    g_Bt[d*96 + 64 + h] = bv[i];
    g_BoT[d*32 + h]     = bo[i];
}

// ---------------- kernel 3: R = x @ Bt  ([4096,1024] x [1024,96]) -------------------
__global__ void __launch_bounds__(384) k_res96(const float* __restrict__ x) {
    extern __shared__ float xs[];     // [16][1024]
    int t0 = blockIdx.x * 16;
    const float4* xg = (const float4*)(x + (size_t)t0 * Cdim);
    float4* s4 = (float4*)xs;
    for (int i = threadIdx.x; i < 4096; i += 384) s4[i] = xg[i];
    __syncthreads();
    int j  = threadIdx.x % 96;
    int tg = threadIdx.x / 96;
    const float* xr0 = xs + (tg*4 + 0)*1024;
    const float* xr1 = xs + (tg*4 + 1)*1024;
    const float* xr2 = xs + (tg*4 + 2)*1024;
    const float* xr3 = xs + (tg*4 + 3)*1024;
    float a0 = 0.f, a1 = 0.f, a2 = 0.f, a3 = 0.f;
    #pragma unroll 8
    for (int i = 0; i < 1024; i++) {
        float b = g_Bt[i*96 + j];
        a0 += xr0[i] * b;
        a1 += xr1[i] * b;
        a2 += xr2[i] * b;
        a3 += xr3[i] * b;
    }
    g_R[(size_t)(t0 + tg*4    )*96 + j] = a0;
    g_R[(size_t)(t0 + tg*4 + 1)*96 + j] = a1;
    g_R[(size_t)(t0 + tg*4 + 2)*96 + j] = a2;
    g_R[(size_t)(t0 + tg*4 + 3)*96 + j] = a3;
}

// ---------------- kernel 6: Ro = att @ BoT ------------------------------------------
__global__ void __launch_bounds__(256) k_res32() {
    extern __shared__ float xs[];     // [16][1024]
    int t0 = blockIdx.x * 16;
    const float4* xg = (const float4*)(g_att + (size_t)t0 * Cdim);
    float4* s4 = (float4*)xs;
    for (int i = threadIdx.x; i < 4096; i += 256) s4[i] = xg[i];
    __syncthreads();
    int h  = threadIdx.x & 31;
    int tg = threadIdx.x >> 5;
    const float* xr0 = xs + (tg*2    )*1024;
    const float* xr1 = xs + (tg*2 + 1)*1024;
    float a0 = 0.f, a1 = 0.f;
    #pragma unroll 8
    for (int i = 0; i < 1024; i++) {
        float b = g_BoT[i*32 + h];
        a0 += xr0[i] * b;
        a1 += xr1[i] * b;
    }
    g_Ro[(size_t)(t0 + tg*2    )*32 + h] = a0;
    g_Ro[(size_t)(t0 + tg*2 + 1)*32 + h] = a1;
}

// ---------------- kernel 4/7: expand resonance --------------------------------------
// which 0: q plain. which 1: k with within-8 d-permutation (R5 layout). which 2:
// V TRANSPOSED [bh][d][L] with within-8 key(L)-permutation. which 3: final out.
__global__ void __launch_bounds__(256) k_proj(int which, float* __restrict__ dout) {
    __shared__ float Rs[8][32];
    int t0 = blockIdx.x * 8;
    int tid = threadIdx.x;
    const float* Rsrc; int rstride, roff; const float* w; float* out;
    if (which < 3) { Rsrc = g_R;  rstride = 96; roff = which*32; w = g_w[which]; out = g_qkv[which]; }
    else           { Rsrc = g_Ro; rstride = 32; roff = 0;        w = g_w[3];     out = dout; }

    {
        int t = tid >> 5, h = tid & 31;
        Rs[t][h] = Rsrc[(size_t)(t0 + t)*rstride + roff + h];
    }
    __syncthreads();

    int c0 = tid * 4;
    float acc[8][4];
    #pragma unroll
    for (int t = 0; t < 8; t++)
        #pragma unroll
        for (int j = 0; j < 4; j++) acc[t][j] = 0.f;

    #pragma unroll
    for (int h = 0; h < 32; h++) {
        float4 w4 = *(const float4*)&w[h*Cdim + c0];
        #pragma unroll
        for (int t = 0; t < 8; t++) {
            float r = Rs[t][h];
            acc[t][0] += r * w4.x;
            acc[t][1] += r * w4.y;
            acc[t][2] += r * w4.z;
            acc[t][3] += r * w4.w;
        }
    }
    if (which == 1) {
        // K: permuted scalar stores: col c0+j -> (col&~7) + 2*j + (tid&1)
        int base = (c0 & ~7) + (tid & 1);
        #pragma unroll
        for (int t = 0; t < 8; t++) {
            float* op = out + (size_t)(t0 + t)*Cdim;
            #pragma unroll
            for (int j = 0; j < 4; j++) op[base + 2*j] = acc[t][j];
        }
    } else if (which == 2) {
        // V: transposed [bh][d][L], tokens t0..t0+7 scattered to permuted L slots
        int b  = t0 >> 11;
        int l0 = t0 & 2047;
        int hh = c0 >> 6;
        int d0 = c0 & 63;
        float* vt = out + (size_t)(b*NH + hh) * HD * Ls;
        #pragma unroll
        for (int j = 0; j < 4; j++) {
            float* row = vt + (size_t)(d0 + j) * Ls + l0;
            #pragma unroll
            for (int t = 0; t < 8; t++) {
                int p = (t < 4) ? 2*t : 2*t - 7;
                row[p] = acc[t][j];
            }
        }
    } else {
        #pragma unroll
        for (int t = 0; t < 8; t++) {
            float4 v = make_float4(acc[t][0], acc[t][1], acc[t][2], acc[t][3]);
            *(float4*)(out + (size_t)(t0 + t)*Cdim + c0) = v;
        }
    }
}

// ---------------- kernel 5: flash attention, tf32 mma.sync --------------------------
// SST=72. K smem [key][d] (d-permuted). V smem [d][key] (key-permuted) -> LDS.64 frags.
// Softmax in exp2 domain: scale*log2e folded into Q.
#define SST 72
#define KVBUF (2*64*SST)
__global__ void __launch_bounds__(256, 2) k_attn() {
    extern __shared__ float smem[];
    float* QPs = smem;                 // [128][72]: Q (prologue) then P (warp-local)

    int qt = blockIdx.x;
    int bh = blockIdx.y;
    int b = bh >> 4, h = bh & 15;
    const float* __restrict__ Qg = g_qkv[0] + (size_t)b*Ls*Cdim + h*HD;
    const float* __restrict__ Kg = g_qkv[1] + (size_t)b*Ls*Cdim + h*HD;
    const float* __restrict__ Vt = g_qkv[2] + (size_t)bh*HD*Ls;   // [d][L] key-permuted
    float* __restrict__ Og = g_att + (size_t)b*Ls*Cdim + h*HD;

    int tid = threadIdx.x;
    int wid = tid >> 5, lane = tid & 31;
    int g = lane >> 2, c = lane & 3;
    int wr = wid * 16;
    const float qscale = 0.125f * 1.44269504088896340736f;   // scale * log2(e)

    auto loadKV = [&](int kt, int buf) {
        float* Kb = smem + 128*SST + buf*KVBUF;
        float* Vb = Kb + 64*SST;
        #pragma unroll
        for (int u = 0; u < 8; u++) {
            int i = tid + u*256;       // 0..2047
            int m = i >> 10;           // 0 = K, 1 = V
            int j = i & 1023;
            int r = j >> 4, ch = j & 15;
            const float* src = m ? (Vt + (size_t)r*Ls + kt*64 + ch*4)
                                 : (Kg + (size_t)(kt*64 + r)*Cdim + ch*4);
            float* dst = (m ? Vb : Kb) + r*SST + ch*4;
            cp16(dst, src);
        }
        asm volatile("cp.async.commit_group;");
    };

    loadKV(0, 0);

    // ---- prologue: Q tile -> smem (scaled by scale*log2e, tf32 RNA) ----
    for (int i = tid; i < 2048; i += 256) {
        int r = i >> 4, f4 = i & 15;
        float4 v = *(const float4*)(Qg + (size_t)(qt*128 + r)*Cdim + f4*4);
        float* dst = &QPs[r*SST + f4*4];
        dst[0] = f2tf32(v.x*qscale); dst[1] = f2tf32(v.y*qscale);
        dst[2] = f2tf32(v.z*qscale); dst[3] = f2tf32(v.w*qscale);
    }
    __syncthreads();

    unsigned qf[8][4];
    #pragma unroll
    for (int kg = 0; kg < 8; kg++) {
        qf[kg][0] = __float_as_uint(QPs[(wr+g  )*SST + kg*8 + c    ]);
        qf[kg][1] = __float_as_uint(QPs[(wr+g+8)*SST + kg*8 + c    ]);
        qf[kg][2] = __float_as_uint(QPs[(wr+g  )*SST + kg*8 + c + 4]);
        qf[kg][3] = __float_as_uint(QPs[(wr+g+8)*SST + kg*8 + c + 4]);
    }

    float m0 = -1e30f, m1 = -1e30f, l0 = 0.f, l1 = 0.f;
    float O[8][4];
    #pragma unroll
    for (int nt = 0; nt < 8; nt++)
        #pragma unroll
        for (int j = 0; j < 4; j++) O[nt][j] = 0.f;

    // P store positions for keys 2c, 2c+1 under perm r -> (r<4 ? 2r : 2r-7)
    int pos0 = (c < 2) ? 4*c : 4*c - 7;

    for (int kt = 0; kt < 32; kt++) {
        __syncthreads();
        if (kt + 1 < 32) {
            loadKV(kt + 1, (kt + 1) & 1);
            asm volatile("cp.async.wait_group 1;");
        } else {
            asm volatile("cp.async.wait_group 0;");
        }
        __syncthreads();

        const float* Ks = smem + 128*SST + (kt & 1)*KVBUF;
        const float* Vs = Ks + 64*SST;

        // ---- S = Q . K^T (log2-domain scores; K d-permuted -> LDS.64 B-frags) ----
        float S[8][4];
        #pragma unroll
        for (int nt = 0; nt < 8; nt++)
            #pragma unroll
            for (int j = 0; j < 4; j++) S[nt][j] = 0.f;

        #pragma unroll
        for (int kg = 0; kg < 8; kg++) {
            #pragma unroll
            for (int nt = 0; nt < 8; nt++) {
                float2 kv2 = *(const float2*)&Ks[(nt*8+g)*SST + kg*8 + 2*c];
                mma_tf32(S[nt], qf[kg],
                         __float_as_uint(kv2.x), __float_as_uint(kv2.y));
            }
        }

        // ---- online softmax (exp2 domain) ----
        float mx0 = -1e30f, mx1 = -1e30f;
        #pragma unroll
        for (int nt = 0; nt < 8; nt++) {
            mx0 = fmaxf(mx0, fmaxf(S[nt][0], S[nt][1]));
            mx1 = fmaxf(mx1, fmaxf(S[nt][2], S[nt][3]));
        }
        mx0 = fmaxf(mx0, __shfl_xor_sync(0xffffffffu, mx0, 1));
        mx0 = fmaxf(mx0, __shfl_xor_sync(0xffffffffu, mx0, 2));
        mx1 = fmaxf(mx1, __shfl_xor_sync(0xffffffffu, mx1, 1));
        mx1 = fmaxf(mx1, __shfl_xor_sync(0xffffffffu, mx1, 2));

        float mn0 = fmaxf(m0, mx0), mn1 = fmaxf(m1, mx1);
        float a0 = ex2f(m0 - mn0), a1 = ex2f(m1 - mn1);
        m0 = mn0; m1 = mn1;

        float s0 = 0.f, s1 = 0.f;
        #pragma unroll
        for (int nt = 0; nt < 8; nt++) {
            S[nt][0] = ex2f(S[nt][0] - mn0); s0 += S[nt][0];
            S[nt][1] = ex2f(S[nt][1] - mn0); s0 += S[nt][1];
            S[nt][2] = ex2f(S[nt][2] - mn1); s1 += S[nt][2];
            S[nt][3] = ex2f(S[nt][3] - mn1); s1 += S[nt][3];
        }
        s0 += __shfl_xor_sync(0xffffffffu, s0, 1);
        s0 += __shfl_xor_sync(0xffffffffu, s0, 2);
        s1 += __shfl_xor_sync(0xffffffffu, s1, 1);
        s1 += __shfl_xor_sync(0xffffffffu, s1, 2);
        l0 = l0*a0 + s0;
        l1 = l1*a1 + s1;
        #pragma unroll
        for (int nt = 0; nt < 8; nt++) {
            O[nt][0] *= a0; O[nt][1] *= a0;
            O[nt][2] *= a1; O[nt][3] *= a1;
        }

        // ---- store P at permuted key positions (pos0, pos0+2) ----
        #pragma unroll
        for (int nt = 0; nt < 8; nt++) {
            QPs[(wr+g  )*SST + nt*8 + pos0    ] = S[nt][0];
            QPs[(wr+g  )*SST + nt*8 + pos0 + 2] = S[nt][1];
            QPs[(wr+g+8)*SST + nt*8 + pos0    ] = S[nt][2];
            QPs[(wr+g+8)*SST + nt*8 + pos0 + 2] = S[nt][3];
        }
        __syncwarp();

        // ---- O += P . V  (P and V frags both via LDS.64 at permuted positions) ----
        #pragma unroll
        for (int kg = 0; kg < 8; kg++) {
            float2 p0 = *(const float2*)&QPs[(wr+g  )*SST + kg*8 + 2*c];
            float2 p1 = *(const float2*)&QPs[(wr+g+8)*SST + kg*8 + 2*c];
            unsigned pf[4] = { __float_as_uint(p0.x), __float_as_uint(p1.x),
                               __float_as_uint(p0.y), __float_as_uint(p1.y) };
            #pragma unroll
            for (int nt = 0; nt < 8; nt++) {
                float2 v2 = *(const float2*)&Vs[(nt*8 + g)*SST + kg*8 + 2*c];
                mma_tf32(O[nt], pf,
                         __float_as_uint(v2.x), __float_as_uint(v2.y));
            }
        }
        __syncwarp();
    }

    // ---- epilogue ----
    float i0 = 1.f / l0, i1 = 1.f / l1;
    #pragma unroll
    for (int nt = 0; nt < 8; nt++) {
        float2 o0 = make_float2(O[nt][0]*i0, O[nt][1]*i0);
        float2 o1 = make_float2(O[nt][2]*i1, O[nt][3]*i1);
        *(float2*)(Og + (size_t)(qt*128 + wr + g    )*Cdim + nt*8 + 2*c) = o0;
        *(float2*)(Og + (size_t)(qt*128 + wr + g + 8)*Cdim + nt*8 + 2*c) = o1;
    }
}

// ---------------- launch -------------------------------------------------------------
extern "C" void kernel_launch(void* const* d_in, const int* in_sizes, int n_in,
                              void* d_out, int out_size) {
    const float* x  = (const float*)d_in[0];
    const float* bq = (const float*)d_in[1];
    const float* pq = (const float*)d_in[2];
    const float* aq = (const float*)d_in[3];
    const float* bk = (const float*)d_in[4];
    const float* pk = (const float*)d_in[5];
    const float* ak = (const float*)d_in[6];
    const float* bv = (const float*)d_in[7];
    const float* pv = (const float*)d_in[8];
    const float* av = (const float*)d_in[9];
    const float* bo = (const float*)d_in[10];
    const float* po = (const float*)d_in[11];
    const float* ao = (const float*)d_in[12];
    float* out = (float*)d_out;

    const int ATTN_SMEM = (128*SST + 2*KVBUF) * 4;   // 110592 B

    static bool attr_set = false;
    if (!attr_set) {
        cudaFuncSetAttribute(k_attn,  cudaFuncAttributeMaxDynamicSharedMemorySize, ATTN_SMEM);
        cudaFuncSetAttribute(k_res96, cudaFuncAttributeMaxDynamicSharedMemorySize, 65536);
        cudaFuncSetAttribute(k_res32, cudaFuncAttributeMaxDynamicSharedMemorySize, 65536);
        attr_set = true;
    }

    k_w  <<<128, 256>>>(pq, aq, pk, ak, pv, av, po, ao);
    k_tr <<<128, 256>>>(bq, bk, bv, bo);
    k_res96<<<TOK/16, 384, 65536>>>(x);
    k_proj<<<TOK/8, 256>>>(0, out);
    k_proj<<<TOK/8, 256>>>(1, out);
    k_proj<<<TOK/8, 256>>>(2, out);
    k_attn<<<dim3(Ls/128, Bsz*NH), 256, ATTN_SMEM>>>();
    k_res32<<<TOK/16, 256, 65536>>>();
    k_proj<<<TOK/8, 256>>>(3, out);
}

// round 12
// speedup vs baseline: 1.5496x; 1.5496x over previous
#include <cuda_runtime.h>
#include <cuda_fp16.h>
#include <math.h>

#define Bsz   2
#define Ls    2048
#define Cdim  1024
#define NH    16
#define HD    64
#define HARM  32
#define TOK   (Bsz*Ls)   // 4096

// ---------------- device scratch ----------------------------------------------------
__device__ float  g_w[4][HARM*Cdim];     // w transposed: [h][o]
__device__ float  g_Bt[Cdim*96];         // stacked qkv basis, transposed
__device__ float  g_BoT[Cdim*HARM];      // basis_o transposed
__device__ float  g_R[TOK*96];           // qkv resonances
__device__ __half g_q[TOK*Cdim];         // Q fp16, pre-scaled by scale*log2e, d-pair-permuted
__device__ __half g_k[TOK*Cdim];         // K fp16, d-pair-permuted
__device__ __half g_v[Bsz*NH*HD*Ls];     // V fp16, transposed [bh][d][L], L-pair-permuted
__device__ float  g_att[TOK*Cdim];       // attention output [B,L,C] fp32
__device__ float  g_Ro[TOK*HARM];        // output-projection resonance

#define QSCALE (0.125f * 1.44269504088896340736f)   // headdim^-0.5 * log2(e)

__device__ __forceinline__ float ex2f(float x) {
    float r; asm("ex2.approx.f32 %0, %1;" : "=f"(r) : "f"(x)); return r;
}
__device__ __forceinline__ unsigned h2pk(float lo, float hi) {
    unsigned r; asm("cvt.rn.f16x2.f32 %0, %1, %2;" : "=r"(r) : "f"(hi), "f"(lo)); return r;
}
__device__ __forceinline__ void mma_f16(float d[4], const unsigned a[4],
                                        unsigned b0, unsigned b1) {
    asm("mma.sync.aligned.m16n8k16.row.col.f32.f16.f16.f32 "
        "{%0,%1,%2,%3}, {%4,%5,%6,%7}, {%8,%9}, {%0,%1,%2,%3};"
        : "+f"(d[0]), "+f"(d[1]), "+f"(d[2]), "+f"(d[3])
        : "r"(a[0]), "r"(a[1]), "r"(a[2]), "r"(a[3]), "r"(b0), "r"(b1));
}
__device__ __forceinline__ void cp16(float* dst, const void* src) {
    unsigned d = (unsigned)__cvta_generic_to_shared(dst);
    asm volatile("cp.async.cg.shared.global [%0], [%1], 16;" :: "r"(d), "l"(src));
}

// ---------------- kernel 1: w = amp * cos(phase), stored transposed [h][o] ----------
__global__ void k_w(const float* __restrict__ pq, const float* __restrict__ aq,
                    const float* __restrict__ pk, const float* __restrict__ ak,
                    const float* __restrict__ pv, const float* __restrict__ av,
                    const float* __restrict__ po, const float* __restrict__ ao) {
    int i = blockIdx.x * blockDim.x + threadIdx.x;
    int o = i >> 5, h = i & 31;
    int j = h * Cdim + o;
    g_w[0][j] = aq[i] * cosf(pq[i]);
    g_w[1][j] = ak[i] * cosf(pk[i]);
    g_w[2][j] = av[i] * cosf(pv[i]);
    g_w[3][j] = ao[i] * cosf(po[i]);
}

// ---------------- kernel 2: transpose + stack bases ---------------------------------
__global__ void k_tr(const float* __restrict__ bq, const float* __restrict__ bk,
                     const float* __restrict__ bv, const float* __restrict__ bo) {
    int i = blockIdx.x * blockDim.x + threadIdx.x;
    int h = i >> 10, d = i & 1023;
    g_Bt[d*96 + h]      = bq[i];
    g_Bt[d*96 + 32 + h] = bk[i];
    g_Bt[d*96 + 64 + h] = bv[i];
    g_BoT[d*32 + h]     = bo[i];
}

// ---------------- kernel 3: R = x @ Bt  ([4096,1024] x [1024,96]) -------------------
__global__ void __launch_bounds__(384) k_res96(const float* __restrict__ x) {
    extern __shared__ float xs[];     // [16][1024]
    int t0 = blockIdx.x * 16;
    const float4* xg = (const float4*)(x + (size_t)t0 * Cdim);
    float4* s4 = (float4*)xs;
    for (int i = threadIdx.x; i < 4096; i += 384) s4[i] = xg[i];
    __syncthreads();
    int j  = threadIdx.x % 96;
    int tg = threadIdx.x / 96;
    const float* x0 = xs + (tg*4 + 0)*1024;
    const float* x1 = xs + (tg*4 + 1)*1024;
    const float* x2 = xs + (tg*4 + 2)*1024;
    const float* x3 = xs + (tg*4 + 3)*1024;
    float a0 = 0.f, a1 = 0.f, a2 = 0.f, a3 = 0.f;
    #pragma unroll 8
    for (int i = 0; i < 1024; i++) {
        float b = g_Bt[i*96 + j];
        a0 += x0[i] * b; a1 += x1[i] * b; a2 += x2[i] * b; a3 += x3[i] * b;
    }
    g_R[(size_t)(t0 + tg*4    )*96 + j] = a0;
    g_R[(size_t)(t0 + tg*4 + 1)*96 + j] = a1;
    g_R[(size_t)(t0 + tg*4 + 2)*96 + j] = a2;
    g_R[(size_t)(t0 + tg*4 + 3)*96 + j] = a3;
}

// ---------------- kernel 6: Ro = att @ BoT ------------------------------------------
__global__ void __launch_bounds__(256) k_res32() {
    extern __shared__ float xs[];     // [16][1024]
    int t0 = blockIdx.x * 16;
    const float4* xg = (const float4*)(g_att + (size_t)t0 * Cdim);
    float4* s4 = (float4*)xs;
    for (int i = threadIdx.x; i < 4096; i += 256) s4[i] = xg[i];
    __syncthreads();
    int h  = threadIdx.x & 31;
    int tg = threadIdx.x >> 5;
    const float* x0 = xs + (tg*2    )*1024;
    const float* x1 = xs + (tg*2 + 1)*1024;
    float a0 = 0.f, a1 = 0.f;
    #pragma unroll 8
    for (int i = 0; i < 1024; i++) {
        float b = g_BoT[i*32 + h];
        a0 += x0[i] * b; a1 += x1[i] * b;
    }
    g_Ro[(size_t)(t0 + tg*2    )*32 + h] = a0;
    g_Ro[(size_t)(t0 + tg*2 + 1)*32 + h] = a1;
}

// ---------------- kernel 4/7: expand resonance --------------------------------------
// which 0: Q fp16 (pre-scaled, d-pair-permuted). which 1: K fp16 (d-pair-permuted).
// which 2: V fp16 transposed [bh][d][L], L-pair-permuted. which 3: final fp32 out.
// Pair permutation within a 16-element group: pair p (elems 2p,2p+1) -> slot
// (p<4 ? 2p : 2p-7), so logical pairs (p, p+4) land adjacent -> 64-bit frag loads.
__global__ void __launch_bounds__(256) k_proj(int which, float* __restrict__ dout) {
    __shared__ float Rs[8][32];
    int t0 = blockIdx.x * 8;
    int tid = threadIdx.x;
    const float* Rsrc; int rstride, roff; const float* w;
    if (which < 3) { Rsrc = g_R;  rstride = 96; roff = which*32; w = g_w[which]; }
    else           { Rsrc = g_Ro; rstride = 32; roff = 0;        w = g_w[3];     }

    {
        int t = tid >> 5, h = tid & 31;
        Rs[t][h] = Rsrc[(size_t)(t0 + t)*rstride + roff + h];
    }
    __syncthreads();

    int c0 = tid * 4;
    float acc[8][4];
    #pragma unroll
    for (int t = 0; t < 8; t++)
        #pragma unroll
        for (int j = 0; j < 4; j++) acc[t][j] = 0.f;

    #pragma unroll
    for (int h = 0; h < 32; h++) {
        float4 w4 = *(const float4*)&w[h*Cdim + c0];
        #pragma unroll
        for (int t = 0; t < 8; t++) {
            float r = Rs[t][h];
            acc[t][0] += r * w4.x;
            acc[t][1] += r * w4.y;
            acc[t][2] += r * w4.z;
            acc[t][3] += r * w4.w;
        }
    }

    if (which == 0 || which == 1) {
        __half* out = (which == 0) ? g_q : g_k;
        float s = (which == 0) ? QSCALE : 1.0f;
        int p0 = (c0 >> 1) & 7;            // even pair: slot 2*p0
        int p1 = p0 + 1;                   // odd pair
        int s0 = (p0 < 4) ? 2*p0 : 2*p0 - 7;
        int s1 = (p1 < 4) ? 2*p1 : 2*p1 - 7;
        int base = c0 & ~15;
        #pragma unroll
        for (int t = 0; t < 8; t++) {
            __half* op = out + (size_t)(t0 + t)*Cdim;
            *(unsigned*)(op + base + 2*s0) = h2pk(acc[t][0]*s, acc[t][1]*s);
            *(unsigned*)(op + base + 2*s1) = h2pk(acc[t][2]*s, acc[t][3]*s);
        }
    } else if (which == 2) {
        int bb = t0 >> 11, l0 = t0 & 2047, hh = c0 >> 6, d0 = c0 & 63;
        __half* vt = g_v + (size_t)(bb*NH + hh) * HD * Ls;
        int lbase = l0 & ~15;
        #pragma unroll
        for (int tt = 0; tt < 8; tt += 2) {
            int pg = ((l0 + tt) >> 1) & 7;
            int slot = (pg < 4) ? 2*pg : 2*pg - 7;
            int lp = lbase + 2*slot;
            #pragma unroll
            for (int j = 0; j < 4; j++)
                *(unsigned*)(vt + (size_t)(d0 + j)*Ls + lp) =
                    h2pk(acc[tt][j], acc[tt+1][j]);
        }
    } else {
        #pragma unroll
        for (int t = 0; t < 8; t++)
            *(float4*)(dout + (size_t)(t0 + t)*Cdim + c0) =
                make_float4(acc[t][0], acc[t][1], acc[t][2], acc[t][3]);
    }
}

// ---------------- kernel 5: flash attention, fp16 mma m16n8k16 ----------------------
// grid (16, 32), 256 threads = 8 warps x 16 q-rows. No Q/P smem: Q frags via LDG.64
// from permuted gmem; P repacked register-locally (C-frag == A-frag layout for k16).
// KV smem: 4 buffers, 64 rows x 40 units (row stride 40 = 8 mod 32 -> conflict-free).
#define KVU 2560
#define ATTN_SMEM (4*KVU*4)   // 40960 B
__global__ void __launch_bounds__(256, 2) k_attn() {
    extern __shared__ float smem[];

    int qt = blockIdx.x, bh = blockIdx.y;
    int b = bh >> 4, h = bh & 15;
    const __half* __restrict__ Qg = g_q + (size_t)(b*Ls + qt*128)*Cdim + h*HD;
    const __half* __restrict__ Kg = g_k + (size_t)b*Ls*Cdim + h*HD;
    const __half* __restrict__ Vt = g_v + (size_t)bh*HD*Ls;
    float* __restrict__ Og = g_att + (size_t)(b*Ls + qt*128)*Cdim + h*HD;

    int tid = threadIdx.x, wid = tid >> 5, lane = tid & 31;
    int g = lane >> 2, c = lane & 3;
    int wr = wid * 16;

    auto loadKV = [&](int kt, int buf) {
        float* Kb = smem + buf*KVU;
        float* Vb = smem + 2*KVU + buf*KVU;
        #pragma unroll
        for (int u = 0; u < 4; u++) {
            int i = tid + u*256;          // 0..1023 chunks of 16B
            int m = i >> 9, j = i & 511;
            int r = j >> 3, ch = j & 7;
            const __half* src = m ? (Vt + (size_t)r*Ls + kt*64 + ch*8)
                                  : (Kg + (size_t)(kt*64 + r)*Cdim + ch*8);
            cp16((m ? Vb : Kb) + r*40 + ch*4, src);
        }
        asm volatile("cp.async.commit_group;");
    };

    loadKV(0, 0);

    // Q A-fragments: 4 k-groups x {a0,a1,a2,a3}, straight from permuted gmem
    unsigned qf[4][4];
    #pragma unroll
    for (int kg = 0; kg < 4; kg++) {
        const __half* r0 = Qg + (size_t)(wr + g)*Cdim + kg*16 + 4*c;
        uint2 lo = *(const uint2*)r0;
        uint2 hi = *(const uint2*)(r0 + 8*Cdim);
        qf[kg][0] = lo.x; qf[kg][1] = hi.x; qf[kg][2] = lo.y; qf[kg][3] = hi.y;
    }

    float m0 = -1e30f, m1 = -1e30f, l0 = 0.f, l1 = 0.f;
    float O[8][4];
    #pragma unroll
    for (int nt = 0; nt < 8; nt++)
        #pragma unroll
        for (int j = 0; j < 4; j++) O[nt][j] = 0.f;

    for (int kt = 0; kt < 32; kt++) {
        __syncthreads();
        if (kt + 1 < 32) {
            loadKV(kt + 1, (kt + 1) & 1);
            asm volatile("cp.async.wait_group 1;");
        } else {
            asm volatile("cp.async.wait_group 0;");
        }
        __syncthreads();

        const float* Ks = smem + (kt & 1)*KVU;
        const float* Vs = smem + 2*KVU + (kt & 1)*KVU;

        // ---- S = Q . K^T (log2-domain; 32 MMAs) ----
        float S[8][4];
        #pragma unroll
        for (int nt = 0; nt < 8; nt++)
            #pragma unroll
            for (int j = 0; j < 4; j++) S[nt][j] = 0.f;

        #pragma unroll
        for (int kg = 0; kg < 4; kg++) {
            #pragma unroll
            for (int nt = 0; nt < 8; nt++) {
                uint2 bb = *(const uint2*)&Ks[(nt*8 + g)*40 + kg*8 + 2*c];
                mma_f16(S[nt], qf[kg], bb.x, bb.y);
            }
        }

        // ---- online softmax (exp2 domain) ----
        float mx0 = -1e30f, mx1 = -1e30f;
        #pragma unroll
        for (int nt = 0; nt < 8; nt++) {
            mx0 = fmaxf(mx0, fmaxf(S[nt][0], S[nt][1]));
            mx1 = fmaxf(mx1, fmaxf(S[nt][2], S[nt][3]));
        }
        mx0 = fmaxf(mx0, __shfl_xor_sync(0xffffffffu, mx0, 1));
        mx0 = fmaxf(mx0, __shfl_xor_sync(0xffffffffu, mx0, 2));
        mx1 = fmaxf(mx1, __shfl_xor_sync(0xffffffffu, mx1, 1));
        mx1 = fmaxf(mx1, __shfl_xor_sync(0xffffffffu, mx1, 2));

        float mn0 = fmaxf(m0, mx0), mn1 = fmaxf(m1, mx1);
        float a0 = ex2f(m0 - mn0), a1 = ex2f(m1 - mn1);
        m0 = mn0; m1 = mn1;

        float s0 = 0.f, s1 = 0.f;
        #pragma unroll
        for (int nt = 0; nt < 8; nt++) {
            S[nt][0] = ex2f(S[nt][0] - mn0); s0 += S[nt][0];
            S[nt][1] = ex2f(S[nt][1] - mn0); s0 += S[nt][1];
            S[nt][2] = ex2f(S[nt][2] - mn1); s1 += S[nt][2];
            S[nt][3] = ex2f(S[nt][3] - mn1); s1 += S[nt][3];
        }
        s0 += __shfl_xor_sync(0xffffffffu, s0, 1);
        s0 += __shfl_xor_sync(0xffffffffu, s0, 2);
        s1 += __shfl_xor_sync(0xffffffffu, s1, 1);
        s1 += __shfl_xor_sync(0xffffffffu, s1, 2);
        l0 = l0*a0 + s0;
        l1 = l1*a1 + s1;
        #pragma unroll
        for (int nt = 0; nt < 8; nt++) {
            O[nt][0] *= a0; O[nt][1] *= a0;
            O[nt][2] *= a1; O[nt][3] *= a1;
        }

        // ---- register repack: S C-frags -> P A-frags (no smem round-trip) ----
        unsigned pf[4][4];
        #pragma unroll
        for (int kg = 0; kg < 4; kg++) {
            pf[kg][0] = h2pk(S[2*kg  ][0], S[2*kg  ][1]);
            pf[kg][1] = h2pk(S[2*kg  ][2], S[2*kg  ][3]);
            pf[kg][2] = h2pk(S[2*kg+1][0], S[2*kg+1][1]);
            pf[kg][3] = h2pk(S[2*kg+1][2], S[2*kg+1][3]);
        }

        // ---- O += P . V (32 MMAs; V B-frags via LDS.64, L-pair-permuted) ----
        #pragma unroll
        for (int kg = 0; kg < 4; kg++) {
            #pragma unroll
            for (int nt = 0; nt < 8; nt++) {
                uint2 bb = *(const uint2*)&Vs[(nt*8 + g)*40 + kg*8 + 2*c];
                mma_f16(O[nt], pf[kg], bb.x, bb.y);
            }
        }
    }

    // ---- epilogue ----
    float i0 = 1.f / l0, i1 = 1.f / l1;
    #pragma unroll
    for (int nt = 0; nt < 8; nt++) {
        float2 o0 = make_float2(O[nt][0]*i0, O[nt][1]*i0);
        float2 o1 = make_float2(O[nt][2]*i1, O[nt][3]*i1);
        *(float2*)(Og + (size_t)(wr + g    )*Cdim + nt*8 + 2*c) = o0;
        *(float2*)(Og + (size_t)(wr + g + 8)*Cdim + nt*8 + 2*c) = o1;
    }
}

// ---------------- launch -------------------------------------------------------------
extern "C" void kernel_launch(void* const* d_in, const int* in_sizes, int n_in,
                              void* d_out, int out_size) {
    const float* x  = (const float*)d_in[0];
    const float* bq = (const float*)d_in[1];
    const float* pq = (const float*)d_in[2];
    const float* aq = (const float*)d_in[3];
    const float* bk = (const float*)d_in[4];
    const float* pk = (const float*)d_in[5];
    const float* ak = (const float*)d_in[6];
    const float* bv = (const float*)d_in[7];
    const float* pv = (const float*)d_in[8];
    const float* av = (const float*)d_in[9];
    const float* bo = (const float*)d_in[10];
    const float* po = (const float*)d_in[11];
    const float* ao = (const float*)d_in[12];
    float* out = (float*)d_out;

    static bool attr_set = false;
    if (!attr_set) {
        cudaFuncSetAttribute(k_attn,  cudaFuncAttributeMaxDynamicSharedMemorySize, ATTN_SMEM);
        cudaFuncSetAttribute(k_res96, cudaFuncAttributeMaxDynamicSharedMemorySize, 65536);
        cudaFuncSetAttribute(k_res32, cudaFuncAttributeMaxDynamicSharedMemorySize, 65536);
        attr_set = true;
    }

    k_w  <<<128, 256>>>(pq, aq, pk, ak, pv, av, po, ao);
    k_tr <<<128, 256>>>(bq, bk, bv, bo);
    k_res96<<<TOK/16, 384, 65536>>>(x);
    k_proj<<<TOK/8, 256>>>(0, out);
    k_proj<<<TOK/8, 256>>>(1, out);
    k_proj<<<TOK/8, 256>>>(2, out);
    k_attn<<<dim3(Ls/128, Bsz*NH), 256, ATTN_SMEM>>>();
    k_res32<<<TOK/16, 256, 65536>>>();
    k_proj<<<TOK/8, 256>>>(3, out);
}